// round 9
// baseline (speedup 1.0000x reference)
#include <cuda_runtime.h>
#include <cuda_bf16.h>

// Merged multi-hot embedding bag, sum pooling.
// B=32768, NT=26 tables, 214 packed index columns, DIM=128 fp32.
// Output: [B, 26*128] fp32.
//
// R5 job structure (best: 212.7us). Single change: rows gathered as
// 2x LDG.64 per lane (cols 2*lane, 64+2*lane) instead of 1x LDG.128.
// L1tex model: LDG.128 = 1 issue + 3 replays @2.07 cyc; LDG.64 pair =
// 2 issues + 2 replays -> ~15% fewer L1 wavefront-cycles per row.
//
// Duration-balanced warp jobs:
//  Heavy block (blockIdx < B): ONE sample, 8 warps:
//    w0..w3 : table 20 quarters (25 hots each), combined via smem
//             (subset barrier: bar.sync 1,128 among warps 0..3 ONLY)
//    w4     : t21 (27)
//    w5     : t19 (12) + t1 (2)
//    w6     : t22 (10) + t10 (3)
//    w7     : t14 (9) + t0 (3)
//  Light block (blockIdx >= B): TWO samples, 4 warps each:
//    v0     : t11 (8) + t3 (2) + single t2
//    v1     : t9 (7) + t15 (5)
//    v2     : t4 (6) + t13 (6)
//    v3     : t23 (3) + 10 singles

#define BATCH 32768
#define NT 26
#define TOTAL_COLS 214
#define DIM 128

// columns of the 10 singles handled by light-warp v3
__constant__ int c_s3col[10] = {14,15,16,17,36,57,58,59,212,213};

// one row = 2x LDG.64: lane covers cols [2*lane, 2*lane+1] and [64+2*lane, 64+2*lane+1]
#define ROWF2A(i) ((const float2*)(weights + (long long)(i) * DIM) + lane)
#define ROWF2B(i) ((const float2*)(weights + (long long)(i) * DIM) + 32 + lane)

__device__ __forceinline__ void gather_sum(const int* __restrict__ idxp, int h,
                                           const float* __restrict__ weights, int lane,
                                           float2& oa, float2& ob)
{
    // h <= 32: one coalesced index load, broadcast via shfl
    int iv = 0;
    if (lane < h) iv = __ldg(idxp + lane);
    float2 sa = make_float2(0.f, 0.f);
    float2 sb = make_float2(0.f, 0.f);
    int k = 0;
    for (; k + 4 <= h; k += 4) {
        int i0 = __shfl_sync(0xffffffffu, iv, k);
        int i1 = __shfl_sync(0xffffffffu, iv, k + 1);
        int i2 = __shfl_sync(0xffffffffu, iv, k + 2);
        int i3 = __shfl_sync(0xffffffffu, iv, k + 3);
        float2 a0 = __ldg(ROWF2A(i0));
        float2 b0 = __ldg(ROWF2B(i0));
        float2 a1 = __ldg(ROWF2A(i1));
        float2 b1 = __ldg(ROWF2B(i1));
        float2 a2 = __ldg(ROWF2A(i2));
        float2 b2 = __ldg(ROWF2B(i2));
        float2 a3 = __ldg(ROWF2A(i3));
        float2 b3 = __ldg(ROWF2B(i3));
        sa.x += (a0.x + a1.x) + (a2.x + a3.x);
        sa.y += (a0.y + a1.y) + (a2.y + a3.y);
        sb.x += (b0.x + b1.x) + (b2.x + b3.x);
        sb.y += (b0.y + b1.y) + (b2.y + b3.y);
    }
    for (; k < h; k++) {
        int i0 = __shfl_sync(0xffffffffu, iv, k);
        float2 a0 = __ldg(ROWF2A(i0));
        float2 b0 = __ldg(ROWF2B(i0));
        sa.x += a0.x; sa.y += a0.y;
        sb.x += b0.x; sb.y += b0.y;
    }
    oa = sa; ob = sb;
}

#define STORE_ROW2(t, va, vb) do {                                    \
    float2* _q = (float2*)(orow + (t) * DIM) + lane;                  \
    __stcs(_q,      va);                                              \
    __stcs(_q + 32, vb);                                              \
} while (0)

__device__ __forceinline__ void bag_store(const int* __restrict__ rowidx, int s, int h,
                                          const float* __restrict__ weights, int lane,
                                          float* __restrict__ orow, int t)
{
    float2 sa, sb;
    gather_sum(rowidx + s, h, weights, lane, sa, sb);
    STORE_ROW2(t, sa, sb);
}

__global__ __launch_bounds__(256, 8)
void merged_embed_bag_kernel(const int* __restrict__ indices,
                             const float* __restrict__ weights,
                             float* __restrict__ out)
{
    __shared__ float4 sp[3][32];   // table-20 partials from warps 1..3

    const int blk  = blockIdx.x;
    const int w    = threadIdx.x >> 5;
    const int lane = threadIdx.x & 31;
    const bool heavy = (blk < BATCH);   // heavy blocks dispatched first

    if (heavy) {
        const int b = blk;
        const int* rowidx = indices + (long long)b * TOTAL_COLS;
        float* orow = out + (long long)b * (NT * DIM);

        if (w < 4) {
            // table 20 quarter: cols [72 + 25*w, 72 + 25*w + 25)
            float2 sa, sb;
            gather_sum(rowidx + 72 + 25 * w, 25, weights, lane, sa, sb);
            if (w != 0) sp[w - 1][lane] = make_float4(sa.x, sa.y, sb.x, sb.y);
            // subset barrier: only warps 0..3 (128 threads) participate
            asm volatile("bar.sync 1, 128;" ::: "memory");
            if (w == 0) {
                float4 p0 = sp[0][lane];
                float4 p1 = sp[1][lane];
                float4 p2 = sp[2][lane];
                sa.x += (p0.x + p1.x) + p2.x;
                sa.y += (p0.y + p1.y) + p2.y;
                sb.x += (p0.z + p1.z) + p2.z;
                sb.y += (p0.w + p1.w) + p2.w;
                STORE_ROW2(20, sa, sb);
            }
        } else if (w == 4) {
            bag_store(rowidx, 172, 27, weights, lane, orow, 21);
        } else if (w == 5) {
            bag_store(rowidx, 60, 12, weights, lane, orow, 19);
            bag_store(rowidx, 3, 2, weights, lane, orow, 1);
        } else if (w == 6) {
            bag_store(rowidx, 199, 10, weights, lane, orow, 22);
            bag_store(rowidx, 25, 3, weights, lane, orow, 10);
        } else {
            bag_store(rowidx, 43, 9, weights, lane, orow, 14);
            bag_store(rowidx, 0, 3, weights, lane, orow, 0);
        }
    } else {
        // light block: two samples, 4 warps each
        const int p = blk - BATCH;
        const int b = (p << 1) | (w >> 2);
        const int v = w & 3;
        const int* rowidx = indices + (long long)b * TOTAL_COLS;
        float* orow = out + (long long)b * (NT * DIM);

        if (v == 0) {
            bag_store(rowidx, 28, 8, weights, lane, orow, 11);
            bag_store(rowidx, 6, 2, weights, lane, orow, 3);
            // single: table 2 at col 5
            int i0 = __ldg(rowidx + 5);
            float2 a0 = __ldg(ROWF2A(i0));
            float2 b0 = __ldg(ROWF2B(i0));
            STORE_ROW2(2, a0, b0);
        } else if (v == 1) {
            bag_store(rowidx, 18, 7, weights, lane, orow, 9);
            bag_store(rowidx, 52, 5, weights, lane, orow, 15);
        } else if (v == 2) {
            bag_store(rowidx, 8, 6, weights, lane, orow, 4);
            bag_store(rowidx, 37, 6, weights, lane, orow, 13);
        } else {
            bag_store(rowidx, 209, 3, weights, lane, orow, 23);
            // 10 singles: coalesced idx load + shfl, then independent copies
            int iv = 0;
            if (lane < 10) iv = __ldg(rowidx + c_s3col[lane]);
            int i0 = __shfl_sync(0xffffffffu, iv, 0);
            int i1 = __shfl_sync(0xffffffffu, iv, 1);
            int i2 = __shfl_sync(0xffffffffu, iv, 2);
            int i3 = __shfl_sync(0xffffffffu, iv, 3);
            int i4 = __shfl_sync(0xffffffffu, iv, 4);
            {
                float2 a0 = __ldg(ROWF2A(i0)); float2 b0 = __ldg(ROWF2B(i0));
                float2 a1 = __ldg(ROWF2A(i1)); float2 b1 = __ldg(ROWF2B(i1));
                float2 a2 = __ldg(ROWF2A(i2)); float2 b2 = __ldg(ROWF2B(i2));
                float2 a3 = __ldg(ROWF2A(i3)); float2 b3 = __ldg(ROWF2B(i3));
                STORE_ROW2(5,  a0, b0);
                STORE_ROW2(6,  a1, b1);
                STORE_ROW2(7,  a2, b2);
                STORE_ROW2(8,  a3, b3);
            }
            int i5 = __shfl_sync(0xffffffffu, iv, 5);
            int i6 = __shfl_sync(0xffffffffu, iv, 6);
            int i7 = __shfl_sync(0xffffffffu, iv, 7);
            int i8 = __shfl_sync(0xffffffffu, iv, 8);
            int i9 = __shfl_sync(0xffffffffu, iv, 9);
            {
                float2 a0 = __ldg(ROWF2A(i4)); float2 b0 = __ldg(ROWF2B(i4));
                float2 a1 = __ldg(ROWF2A(i5)); float2 b1 = __ldg(ROWF2B(i5));
                float2 a2 = __ldg(ROWF2A(i6)); float2 b2 = __ldg(ROWF2B(i6));
                float2 a3 = __ldg(ROWF2A(i7)); float2 b3 = __ldg(ROWF2B(i7));
                STORE_ROW2(12, a0, b0);
                STORE_ROW2(16, a1, b1);
                STORE_ROW2(17, a2, b2);
                STORE_ROW2(18, a3, b3);
            }
            {
                float2 a0 = __ldg(ROWF2A(i8)); float2 b0 = __ldg(ROWF2B(i8));
                float2 a1 = __ldg(ROWF2A(i9)); float2 b1 = __ldg(ROWF2B(i9));
                STORE_ROW2(24, a0, b0);
                STORE_ROW2(25, a1, b1);
            }
        }
    }
}

extern "C" void kernel_launch(void* const* d_in, const int* in_sizes, int n_in,
                              void* d_out, int out_size)
{
    const int* indices = nullptr;
    const float* weights = nullptr;
    const long long idx_elems = (long long)BATCH * TOTAL_COLS;
    for (int i = 0; i < n_in; i++) {
        if ((long long)in_sizes[i] == idx_elems) indices = (const int*)d_in[i];
        else weights = (const float*)d_in[i];
    }
    float* out = (float*)d_out;

    const int threads = 256;
    const int blocks = BATCH + BATCH / 2;   // 32768 heavy + 16384 light = 49152

    merged_embed_bag_kernel<<<blocks, threads>>>(indices, weights, out);
}